// round 14
// baseline (speedup 1.0000x reference)
#include <cuda_runtime.h>
#include <cuda_fp16.h>
#include <cstdint>

// Problem constants (fixed by the reference)
#define BB 8
#define CC 128
#define HH 128
#define WW 128
#define PP 32768
#define HW (HH * WW)

// Binning: 8x8 spatial tiles -> 16x16 tiles per batch, 2048 bins total.
#define TILE 8
#define TPD (WW / TILE)            // 16 tiles per dimension
#define BINS_PER_B (TPD * TPD)     // 256
#define NBINS (BB * BINS_PER_B)    // 2048
#define CAP 320                    // bin capacity (mean ~110, huge margin)
#define OOBCAP 65536               // out-of-bounds list capacity (~38K expected)

// Scratch
__device__ __half g_featT[BB * HW * CC];        // [B][HW][C] fp16, 33.5 MB
__device__ int g_count[NBINS + 1];              // per-bin counts + [NBINS]=oob
__device__ unsigned g_binned[NBINS * CAP];      // point indices per bin
__device__ unsigned g_oob[OOBCAP];              // out-of-bounds point indices

static __device__ __forceinline__ __half2 u32_to_h2(unsigned u) {
    return *reinterpret_cast<__half2*>(&u);
}

// ---------------------------------------------------------------------------
// Kernel 1: tiled transpose + f32->fp16:  src[C][HW] -> dstT[HW][C] (half)
// ---------------------------------------------------------------------------
__global__ void transpose_kernel(const float* __restrict__ src) {
    __shared__ float tile[32][129];

    const int b = blockIdx.z;
    const int hw0 = blockIdx.x * 128;
    const int c0 = blockIdx.y * 32;
    const float* sb = src + (size_t)b * CC * HW;
    __half2* db = (__half2*)(g_featT + (size_t)b * HW * CC);

    const int tx = threadIdx.x, ty = threadIdx.y;

#pragma unroll
    for (int jj = 0; jj < 4; jj++) {
        const int c = ty + jj * 8;
        const float4 v = __ldcs((const float4*)&sb[(size_t)(c0 + c) * HW + hw0] + tx);
        tile[c][4 * tx + 0] = v.x;
        tile[c][4 * tx + 1] = v.y;
        tile[c][4 * tx + 2] = v.z;
        tile[c][4 * tx + 3] = v.w;
    }
    __syncthreads();

    const int t = ty * 32 + tx;
    const int col = t & 15;
    const int rowg = t >> 4;
#pragma unroll
    for (int pass = 0; pass < 8; pass++) {
        const int row = rowg + pass * 16;
        const float lo = tile[2 * col][row];
        const float hi = tile[2 * col + 1][row];
        db[(size_t)(hw0 + row) * (CC / 2) + (c0 >> 1) + col] =
            __floats2half2_rn(lo, hi);
    }
}

// ---------------------------------------------------------------------------
// Kernel A: zero bin counters
// ---------------------------------------------------------------------------
__global__ void zero_counts_kernel() {
    for (int i = threadIdx.x; i < NBINS + 1; i += blockDim.x) g_count[i] = 0;
}

// ---------------------------------------------------------------------------
// Kernel B: bin points by spatial tile (in-bounds) or OOB list.
// ---------------------------------------------------------------------------
__global__ __launch_bounds__(256) void bin_kernel(const float* __restrict__ tk_codes) {
    const unsigned FULL = 0xffffffffu;
    const int pidx = blockIdx.x * 256 + threadIdx.x;
    const int lane = threadIdx.x & 31;

    const float2 pt = __ldg(((const float2*)tk_codes) + pidx);
    const float x = pt.x, y = pt.y;
    const bool inb = (x >= 0.0f) & (y >= 0.0f) &
                     (x <= (float)(WW - 1)) & (y <= (float)(HH - 1));

    const unsigned oob_mask = __ballot_sync(FULL, !inb);
    if (inb) {
        const int fxI = (int)floorf(x);
        const int fyI = (int)floorf(y);
        const int tile = (pidx >> 15) * BINS_PER_B + (fyI >> 3) * TPD + (fxI >> 3);
        const int slot = atomicAdd(&g_count[tile], 1);
        if (slot < CAP) g_binned[tile * CAP + slot] = (unsigned)pidx;
    } else {
        // warp-aggregated atomic (single shared counter)
        const int leader = __ffs(oob_mask) - 1;
        int base = 0;
        if (lane == leader) base = atomicAdd(&g_count[NBINS], __popc(oob_mask));
        base = __shfl_sync(oob_mask, base, leader);
        const int off = __popc(oob_mask & ((1u << lane) - 1));
        if (base + off < OOBCAP) g_oob[base + off] = (unsigned)pidx;
    }
}

// ---------------------------------------------------------------------------
// Kernel C: gather, one block per bin. Corner rows live in a 9x9 window
// (20.7KB) -> L1-resident across the block's warps. 8 warps x 8 points
// per pass = 64 points per block pass.
// ---------------------------------------------------------------------------
__global__ __launch_bounds__(256) void gather_kernel(
    const float* __restrict__ tk_codes,   // [B, P, 2]
    float* __restrict__ out)              // [B, P, C]
{
    const unsigned FULL = 0xffffffffu;
    const int bin = blockIdx.x;
    const int warp = threadIdx.x >> 5;
    const int lane = threadIdx.x & 31;

    int npts = g_count[bin];
    if (npts > CAP) npts = CAP;
    if (npts == 0) return;

    const int batch = bin >> 8;
    const uint2* __restrict__ baseT =
        (const uint2*)(g_featT + (size_t)batch * HW * CC);
    float4* __restrict__ o4 = (float4*)out;
    const unsigned* __restrict__ blist = g_binned + (size_t)bin * CAP;

    const int j = lane >> 2;                 // this lane's point (0..7)
    const int k = lane & 3;                  // this lane's corner

    for (int base = warp * 8; base < npts; base += 64) {  // 8 warps x 8 pts
        const int myp = base + j;
        const unsigned pidx = blist[(myp < npts) ? myp : 0];

        const float2 pt = __ldg(((const float2*)tk_codes) + pidx);
        const float x = pt.x, y = pt.y;

        const bool inb = (x >= 0.0f) & (y >= 0.0f) &
                         (x <= (float)(WW - 1)) & (y <= (float)(HH - 1));

        // corner order: (fx,fy),(fx,cy),(cx,fy),(cx,cy)
        const float cxk = (k & 2) ? ceilf(x) : floorf(x);
        const float cyk = (k & 1) ? ceilf(y) : floorf(y);

        int gx = ((int)cxk) % WW;   // matches jnp.fmod on int32
        int gy = ((int)cyk) % HH;
        gx = max(gx, 0);
        gy = max(gy, 0);

        const float dx = x - (float)gx;
        const float dy = y - (float)gy;
        float w = inb ? __fdividef(1.0f, sqrtf(dx * dx + dy * dy) + 1e-10f) : 0.0f;

        float d = w + __shfl_xor_sync(FULL, w, 1);
        d += __shfl_xor_sync(FULL, d, 2);
        if (d == 0.0f) d = 1.0f;
        w *= __fdividef(1.0f, d);

        const int idx = (gy << 7) + gx;      // 14 bits
        const unsigned wbits = (unsigned)__half_as_ushort(__float2half_rn(w));
        const unsigned packed = (wbits << 16) | (unsigned)idx;

        const int nhere = min(8, npts - base);
#pragma unroll
        for (int p = 0; p < 8; p++) {
            if (p >= nhere) break;
            const int s = p * 4;
            const unsigned v0 = __shfl_sync(FULL, packed, s + 0);
            const unsigned v1 = __shfl_sync(FULL, packed, s + 1);
            const unsigned v2 = __shfl_sync(FULL, packed, s + 2);
            const unsigned v3 = __shfl_sync(FULL, packed, s + 3);
            const unsigned pout = __shfl_sync(FULL, pidx, s);

            const __half2 w0 = u32_to_h2(__byte_perm(v0, v0, 0x3232));
            const __half2 w1 = u32_to_h2(__byte_perm(v1, v1, 0x3232));
            const __half2 w2 = u32_to_h2(__byte_perm(v2, v2, 0x3232));
            const __half2 w3 = u32_to_h2(__byte_perm(v3, v3, 0x3232));
            const int i0 = (int)(v0 & 0x3FFFu);
            const int i1 = (int)(v1 & 0x3FFFu);
            const int i2 = (int)(v2 & 0x3FFFu);
            const int i3 = (int)(v3 & 0x3FFFu);

            const uint2 r0 = baseT[(size_t)i0 * 32 + lane];
            const uint2 r1 = baseT[(size_t)i1 * 32 + lane];
            const uint2 r2 = baseT[(size_t)i2 * 32 + lane];
            const uint2 r3 = baseT[(size_t)i3 * 32 + lane];

            __half2 a0 = __hmul2(w0, u32_to_h2(r0.x));
            __half2 a1 = __hmul2(w0, u32_to_h2(r0.y));
            a0 = __hfma2(w1, u32_to_h2(r1.x), a0);
            a1 = __hfma2(w1, u32_to_h2(r1.y), a1);
            a0 = __hfma2(w2, u32_to_h2(r2.x), a0);
            a1 = __hfma2(w2, u32_to_h2(r2.y), a1);
            a0 = __hfma2(w3, u32_to_h2(r3.x), a0);
            a1 = __hfma2(w3, u32_to_h2(r3.y), a1);

            const float2 f0 = __half22float2(a0);
            const float2 f1 = __half22float2(a1);
            __stcs(o4 + (size_t)pout * 32 + lane,
                   make_float4(f0.x, f0.y, f1.x, f1.y));
        }
    }
}

// ---------------------------------------------------------------------------
// Kernel D: zero the output rows of out-of-bounds points (weights all 0).
// ---------------------------------------------------------------------------
__global__ __launch_bounds__(256) void zero_oob_kernel(float* __restrict__ out) {
    const int lane = threadIdx.x & 31;
    const int gwarp = (blockIdx.x * blockDim.x + threadIdx.x) >> 5;
    const int nwarps = (gridDim.x * blockDim.x) >> 5;

    int noob = g_count[NBINS];
    if (noob > OOBCAP) noob = OOBCAP;

    float4* __restrict__ o4 = (float4*)out;
    const float4 z = make_float4(0.f, 0.f, 0.f, 0.f);
    for (int i = gwarp; i < noob; i += nwarps) {
        const unsigned pidx = g_oob[i];
        __stcs(o4 + (size_t)pidx * 32 + lane, z);
    }
}

// ---------------------------------------------------------------------------
extern "C" void kernel_launch(void* const* d_in, const int* in_sizes, int n_in,
                              void* d_out, int out_size) {
    const float* tk_codes = (const float*)d_in[0];   // [B, P, 2] float32
    const float* feat     = (const float*)d_in[1];   // [B, C, H, W] float32
    float* out            = (float*)d_out;           // [B, P, C] float32

    (void)in_sizes; (void)n_in; (void)out_size;

    dim3 tgrid(HW / 128, CC / 32, BB);
    dim3 tblock(32, 8);
    transpose_kernel<<<tgrid, tblock>>>(feat);

    zero_counts_kernel<<<1, 1024>>>();
    bin_kernel<<<(BB * PP) / 256, 256>>>(tk_codes);
    gather_kernel<<<NBINS, 256>>>(tk_codes, out);
    zero_oob_kernel<<<64, 256>>>(out);
}